// round 1
// baseline (speedup 1.0000x reference)
#include <cuda_runtime.h>

#define BDIM 8
#define CDIM 64
#define NDIM 256
#define FDIM 128
#define EPS 1e-5f

// Scratch (allocation-free rule: __device__ globals)
__device__ unsigned char g_mask[BDIM * CDIM * NDIM];  // 131072 bytes
__device__ float2 g_w[BDIM * CDIM];                   // softmax weights per (b,c)
__device__ float  g_S1[BDIM * CDIM];                  // partial BN sum
__device__ float  g_S2[BDIM * CDIM];                  // partial BN sumsq
__device__ float2 g_stat[CDIM];                       // (mean, rstd) per channel

__device__ __forceinline__ float warpsum(float v) {
#pragma unroll
    for (int o = 16; o; o >>= 1) v += __shfl_xor_sync(0xffffffffu, v, o);
    return v;
}

// ---------------------------------------------------------------------------
// Kernel 1: per-(b,c) pass. Computes mask per row, supp/query vector sums,
// scalar sq-sums, softmax weights, and BN partial sums. One block per (b,c).
// ---------------------------------------------------------------------------
__global__ __launch_bounds__(256) void k1(const float* __restrict__ h,
                                          const float* __restrict__ op,
                                          const float* __restrict__ opS,
                                          const float* __restrict__ opQ) {
    const int bc = blockIdx.x;         // b*CDIM + c
    const int c  = bc & (CDIM - 1);
    const int tid = threadIdx.x;
    const int w = tid >> 5, lane = tid & 31;

    const float* hbase = h + (size_t)bc * NDIM * FDIM;
    const float4* op4 = (const float4*)(op + c * 2 * FDIM);
    const float4 olo = op4[lane];       // op[c][0:128]   (source part)
    const float4 ohi = op4[32 + lane];  // op[c][128:256] (h part)

    // s_lo = dot(source, op_lo), computed redundantly per warp (cheap, L1-hot)
    const float4 s0 = ((const float4*)hbase)[lane];
    const float s_lo = warpsum(s0.x * olo.x + s0.y * olo.y + s0.z * olo.z + s0.w * olo.w);

    __shared__ float s_supp[FDIM];
    __shared__ float s_query[FDIM];
    __shared__ float acc[6];  // [suppSq, querySq, tS, tQ, sumSupp, sumQuery]
    for (int i = tid; i < FDIM; i += 256) { s_supp[i] = 0.f; s_query[i] = 0.f; }
    if (tid < 6) acc[tid] = 0.f;
    __syncthreads();

    float4 sp = {0.f, 0.f, 0.f, 0.f}, qr = {0.f, 0.f, 0.f, 0.f};
    float ssq = 0.f, qsq = 0.f;

    // Each warp handles rows n = w + 8*i. Process two rows per iteration for MLP.
#pragma unroll 4
    for (int n0 = w; n0 < NDIM; n0 += 16) {
        const int n1 = n0 + 8;
        const float4 hv0 = ((const float4*)(hbase + (size_t)n0 * FDIM))[lane];
        const float4 hv1 = ((const float4*)(hbase + (size_t)n1 * FDIM))[lane];

        float a0 = warpsum(hv0.x * ohi.x + hv0.y * ohi.y + hv0.z * ohi.z + hv0.w * ohi.w);
        float a1 = warpsum(hv1.x * ohi.x + hv1.y * ohi.y + hv1.z * ohi.z + hv1.w * ohi.w);
        const bool m0 = (s_lo + a0) >= 0.f;
        const bool m1 = (s_lo + a1) >= 0.f;
        const float d0 = hv0.x * hv0.x + hv0.y * hv0.y + hv0.z * hv0.z + hv0.w * hv0.w;
        const float d1 = hv1.x * hv1.x + hv1.y * hv1.y + hv1.z * hv1.z + hv1.w * hv1.w;

        if (m0) { sp.x += hv0.x; sp.y += hv0.y; sp.z += hv0.z; sp.w += hv0.w; ssq += d0; }
        else    { qr.x += hv0.x; qr.y += hv0.y; qr.z += hv0.z; qr.w += hv0.w; qsq += d0; }
        if (m1) { sp.x += hv1.x; sp.y += hv1.y; sp.z += hv1.z; sp.w += hv1.w; ssq += d1; }
        else    { qr.x += hv1.x; qr.y += hv1.y; qr.z += hv1.z; qr.w += hv1.w; qsq += d1; }

        if (lane == 0) {
            g_mask[bc * NDIM + n0] = m0 ? 1 : 0;
            g_mask[bc * NDIM + n1] = m1 ? 1 : 0;
        }
    }

    // Fold per-lane vector partials into smem (128 distinct addresses per warp)
    atomicAdd(&s_supp[lane * 4 + 0], sp.x);
    atomicAdd(&s_supp[lane * 4 + 1], sp.y);
    atomicAdd(&s_supp[lane * 4 + 2], sp.z);
    atomicAdd(&s_supp[lane * 4 + 3], sp.w);
    atomicAdd(&s_query[lane * 4 + 0], qr.x);
    atomicAdd(&s_query[lane * 4 + 1], qr.y);
    atomicAdd(&s_query[lane * 4 + 2], qr.z);
    atomicAdd(&s_query[lane * 4 + 3], qr.w);
    ssq = warpsum(ssq);
    qsq = warpsum(qsq);
    if (lane == 0) { atomicAdd(&acc[0], ssq); atomicAdd(&acc[1], qsq); }
    __syncthreads();

    // Epilogue: supp_attn / query_attn scalars and vector-sum totals
    if (tid < FDIM) {
        const int f = tid;
        const float src = hbase[f];  // source[f], L1-hot
        const float fs = s_supp[f];
        const float fq = s_query[f];
        float tS = (fs * (1.f / NDIM)) * opS[c * 2 * FDIM + f] + src * opS[c * 2 * FDIM + FDIM + f];
        float tQ = (fq * (1.f / NDIM)) * opQ[c * 2 * FDIM + f] + src * opQ[c * 2 * FDIM + FDIM + f];
        float rS = warpsum(tS);
        float rQ = warpsum(tQ);
        float rfs = warpsum(fs);
        float rfq = warpsum(fq);
        if (lane == 0) {
            atomicAdd(&acc[2], rS);
            atomicAdd(&acc[3], rQ);
            atomicAdd(&acc[4], rfs);
            atomicAdd(&acc[5], rfq);
        }
    }
    __syncthreads();

    if (tid == 0) {
        const float sa = acc[2], qa = acc[3];
        const float mx = fmaxf(sa, qa);
        const float e0 = expf(sa - mx), e1 = expf(qa - mx);
        const float inv = 1.f / (e0 + e1);
        const float w0 = e0 * inv, w1 = e1 * inv;
        g_w[bc] = make_float2(w0, w1);
        g_S1[bc] = w0 * acc[4] + w1 * acc[5];
        g_S2[bc] = w0 * w0 * acc[0] + w1 * w1 * acc[1];
    }
}

// ---------------------------------------------------------------------------
// Kernel 2: fold batch partials -> per-channel (mean, rstd). One tiny block.
// ---------------------------------------------------------------------------
__global__ void k2() {
    const int c = threadIdx.x;
    float s1 = 0.f, s2 = 0.f;
#pragma unroll
    for (int b = 0; b < BDIM; b++) {
        s1 += g_S1[b * CDIM + c];
        s2 += g_S2[b * CDIM + c];
    }
    const float inv = 1.f / (float)(BDIM * NDIM * FDIM);
    const float mean = s1 * inv;
    const float var = s2 * inv - mean * mean;
    g_stat[c] = make_float2(mean, rsqrtf(var + EPS));
}

// ---------------------------------------------------------------------------
// Kernel 3: streaming elementwise: elu((h*w - mean)*rstd*gamma + beta)
// ---------------------------------------------------------------------------
__global__ __launch_bounds__(256) void k3(const float* __restrict__ h,
                                          const float* __restrict__ gamma,
                                          const float* __restrict__ beta,
                                          float* __restrict__ out) {
    const int i = blockIdx.x * blockDim.x + threadIdx.x;  // float4 index
    const int e = i << 2;                                 // element index
    const int n = (e >> 7) & (NDIM - 1);
    const int bc = e >> 15;           // (b*CDIM + c); 256*128 = 2^15
    const int c = bc & (CDIM - 1);

    const unsigned char m = g_mask[(bc << 8) + n];
    const float2 wv = g_w[bc];
    const float w = m ? wv.x : wv.y;
    const float2 st = g_stat[c];
    const float gr = gamma[c] * st.y;
    const float scale = w * gr;
    const float shift = beta[c] - st.x * gr;

    const float4 hv = ((const float4*)h)[i];
    float4 y;
    y.x = hv.x * scale + shift;
    y.y = hv.y * scale + shift;
    y.z = hv.z * scale + shift;
    y.w = hv.w * scale + shift;
    y.x = (y.x > 0.f) ? y.x : (__expf(y.x) - 1.f);
    y.y = (y.y > 0.f) ? y.y : (__expf(y.y) - 1.f);
    y.z = (y.z > 0.f) ? y.z : (__expf(y.z) - 1.f);
    y.w = (y.w > 0.f) ? y.w : (__expf(y.w) - 1.f);
    ((float4*)out)[i] = y;
}

extern "C" void kernel_launch(void* const* d_in, const int* in_sizes, int n_in,
                              void* d_out, int out_size) {
    const float* h     = (const float*)d_in[0];
    const float* op    = (const float*)d_in[1];
    const float* opS   = (const float*)d_in[2];
    const float* opQ   = (const float*)d_in[3];
    const float* gamma = (const float*)d_in[4];
    const float* beta  = (const float*)d_in[5];
    float* out = (float*)d_out;

    k1<<<BDIM * CDIM, 256>>>(h, op, opS, opQ);
    k2<<<1, CDIM>>>();
    const int total4 = (BDIM * CDIM * NDIM * FDIM) / 4;  // 4,194,304
    k3<<<total4 / 256, 256>>>(h, gamma, beta, out);
}